// round 1
// baseline (speedup 1.0000x reference)
#include <cuda_runtime.h>
#include <cuda_bf16.h>
#include <cstdint>

// loss = || sum_spatial(input_c) - sum_spatial(target_c) ||^2 / C^2
// input/target: (1, 128, 512, 512) fp32 contiguous.

#define NCH   128
#define HW    (512 * 512)          // 262144 elements per channel
#define SPLIT 8                    // blocks per channel
#define NBLK  (NCH * SPLIT)        // 1024 blocks
#define NTHR  256

// scratch for deterministic two-pass reduction (no cudaMalloc allowed)
__device__ float g_partial[NBLK];

__global__ __launch_bounds__(NTHR) void chan_diff_sum_kernel(
    const float4* __restrict__ in, const float4* __restrict__ tgt)
{
    const int blk = blockIdx.x;              // 0 .. NBLK-1
    const int c   = blk >> 3;                // channel
    const int s   = blk & (SPLIT - 1);       // split within channel

    const int vec_per_chan = HW / 4;         // 65536 float4 per channel
    const int vec_per_blk  = vec_per_chan / SPLIT;  // 8192 float4 per block

    const size_t base = (size_t)c * vec_per_chan + (size_t)s * vec_per_blk;

    float acc = 0.0f;
    // 8192 / 256 = 32 float4 per thread per array; unroll to batch LDGs (MLP)
    #pragma unroll 4
    for (int i = threadIdx.x; i < vec_per_blk; i += NTHR) {
        float4 a = __ldg(in  + base + i);
        float4 b = __ldg(tgt + base + i);
        acc += (a.x - b.x) + (a.y - b.y) + (a.z - b.z) + (a.w - b.w);
    }

    // block reduction
    __shared__ float sm[NTHR / 32];
    #pragma unroll
    for (int o = 16; o > 0; o >>= 1)
        acc += __shfl_down_sync(0xffffffffu, acc, o);
    if ((threadIdx.x & 31) == 0) sm[threadIdx.x >> 5] = acc;
    __syncthreads();
    if (threadIdx.x < NTHR / 32) {
        float v = sm[threadIdx.x];
        #pragma unroll
        for (int o = (NTHR / 64); o > 0; o >>= 1)
            v += __shfl_down_sync(0xffu, v, o);
        if (threadIdx.x == 0) g_partial[blk] = v;
    }
}

__global__ __launch_bounds__(128) void finalize_kernel(float* __restrict__ out)
{
    const int c = threadIdx.x;  // one thread per channel
    float d = 0.0f;
    #pragma unroll
    for (int s = 0; s < SPLIT; s++)
        d += g_partial[c * SPLIT + s];
    float v = d * d;

    __shared__ float sm[4];
    #pragma unroll
    for (int o = 16; o > 0; o >>= 1)
        v += __shfl_down_sync(0xffffffffu, v, o);
    if ((threadIdx.x & 31) == 0) sm[threadIdx.x >> 5] = v;
    __syncthreads();
    if (threadIdx.x == 0) {
        float t = sm[0] + sm[1] + sm[2] + sm[3];
        out[0] = t * (1.0f / (128.0f * 128.0f));
    }
}

extern "C" void kernel_launch(void* const* d_in, const int* in_sizes, int n_in,
                              void* d_out, int out_size)
{
    const float4* in  = (const float4*)d_in[0];
    const float4* tgt = (const float4*)d_in[1];
    float* out = (float*)d_out;

    chan_diff_sum_kernel<<<NBLK, NTHR>>>(in, tgt);
    finalize_kernel<<<1, 128>>>(out);
}

// round 2
// speedup vs baseline: 1.0375x; 1.0375x over previous
#include <cuda_runtime.h>
#include <cuda_bf16.h>
#include <cstdint>

// loss = || sum_spatial(input_c) - sum_spatial(target_c) ||^2 / C^2
// input/target: (1, 128, 512, 512) fp32 contiguous.
// Single fused kernel: per-block partial channel sums -> last block finalizes.

#define NCH   128
#define HW    (512 * 512)          // 262144 elements per channel
#define SPLIT 8                    // blocks per channel
#define NBLK  (NCH * SPLIT)        // 1024 blocks
#define NTHR  256

__device__ float        g_partial[NBLK];
__device__ unsigned int g_count;   // zero-init at load; last block resets it

__global__ __launch_bounds__(NTHR) void fused_loss_kernel(
    const float4* __restrict__ in, const float4* __restrict__ tgt,
    float* __restrict__ out)
{
    const int blk = blockIdx.x;              // 0 .. NBLK-1
    const int c   = blk >> 3;                // channel
    const int s   = blk & (SPLIT - 1);       // split within channel

    const int vec_per_chan = HW / 4;                 // 65536 float4/channel
    const int vec_per_blk  = vec_per_chan / SPLIT;   // 8192 float4/block

    const size_t base = (size_t)c * vec_per_chan + (size_t)s * vec_per_blk;

    float acc = 0.0f;
    // 32 float4 per thread per array; unroll 4 -> 8 LDG.128 in flight (MLP)
    #pragma unroll 4
    for (int i = threadIdx.x; i < vec_per_blk; i += NTHR) {
        float4 a = __ldg(in  + base + i);
        float4 b = __ldg(tgt + base + i);
        acc += (a.x - b.x) + (a.y - b.y) + (a.z - b.z) + (a.w - b.w);
    }

    // ---- block reduction ----
    __shared__ float sm[NTHR / 32];
    #pragma unroll
    for (int o = 16; o > 0; o >>= 1)
        acc += __shfl_down_sync(0xffffffffu, acc, o);
    if ((threadIdx.x & 31) == 0) sm[threadIdx.x >> 5] = acc;
    __syncthreads();

    __shared__ bool s_last;
    if (threadIdx.x == 0) {
        float v = 0.0f;
        #pragma unroll
        for (int w = 0; w < NTHR / 32; w++) v += sm[w];
        g_partial[blk] = v;
        __threadfence();                                // publish partial
        unsigned int t = atomicAdd(&g_count, 1u);
        s_last = (t == (unsigned int)(NBLK - 1));
    }
    __syncthreads();

    // ---- last block finalizes (deterministic fixed-order sums) ----
    if (s_last) {
        float v = 0.0f;
        if (threadIdx.x < NCH) {                        // one thread / channel
            float d = 0.0f;
            #pragma unroll
            for (int k = 0; k < SPLIT; k++)
                d += g_partial[threadIdx.x * SPLIT + k];
            v = d * d;
        }
        // reduce 128 squared values across first 4 warps (others contribute 0)
        #pragma unroll
        for (int o = 16; o > 0; o >>= 1)
            v += __shfl_down_sync(0xffffffffu, v, o);
        if ((threadIdx.x & 31) == 0) sm[threadIdx.x >> 5] = v;
        __syncthreads();
        if (threadIdx.x == 0) {
            float t = sm[0] + sm[1] + sm[2] + sm[3];
            out[0] = t * (1.0f / (128.0f * 128.0f));
            g_count = 0;                                // reset for graph replay
        }
    }
}

extern "C" void kernel_launch(void* const* d_in, const int* in_sizes, int n_in,
                              void* d_out, int out_size)
{
    const float4* in  = (const float4*)d_in[0];
    const float4* tgt = (const float4*)d_in[1];
    float* out = (float*)d_out;

    fused_loss_kernel<<<NBLK, NTHR>>>(in, tgt, out);
}